// round 16
// baseline (speedup 1.0000x reference)
#include <cuda_runtime.h>
#include <math.h>

// Problem dims (fixed)
#define B_   128
#define T_   500
#define NI_  256
#define N_   256
#define M_   (B_*T_)
#define TBN_ ((size_t)T_*B_*N_)

// xw scratch, m-pair interleaved: ULL index p*256+n holds (xw[2p][n], xw[2p+1][n])
__device__ unsigned long long g_xw[(size_t)M_ * N_ / 2];

// Packed fp32x2 helpers
#define FFMA2(d, a, b, c) \
    asm("fma.rn.f32x2 %0, %1, %2, %3;" : "=l"(d) : "l"(a), "l"(b), "l"(c))
#define PACK2(d, s) \
    asm("mov.b64 %0, {%1, %1};" : "=l"(d) : "f"(s))
#define PACKAB(d, lo, hi) \
    asm("mov.b64 %0, {%1, %2};" : "=l"(d) : "f"(lo), "f"(hi))

// ===========================================================================
// Kernel 1: xw = x @ w_in. BM=128, BN=128, BK=16, 256 thr, 8m x 8n microtile.
// 2 CTAs/SM, classic grid (R6 version — best measured ~155us). VERBATIM.
// ===========================================================================
#define ASTRIDE 132
#define ASZ (2*16*ASTRIDE)
#define BSZ (2*16*128)
#define GEMM_SMEM ((ASZ + BSZ) * 4)

__global__ void __launch_bounds__(256, 2)
gemm_xw(const float* __restrict__ A, const float* __restrict__ W)
{
    extern __shared__ float gsm[];
    float* As = gsm;
    float* Bs = gsm + ASZ;

    const int t   = threadIdx.x;
    const int bm  = blockIdx.x << 7;
    const int bn0 = blockIdx.y << 7;
    const int tn  = t & 15;
    const int m0  = (t >> 4) << 3;

    const int amr[2] = { (t) >> 2, (t + 256) >> 2 };
    const int akc    = (t & 3) << 2;
    const int bkr[2] = { t >> 5, (t + 256) >> 5 };
    const int bnc    = (t & 31) << 2;

    unsigned long long acc[4][8];
#pragma unroll
    for (int e = 0; e < 4; e++)
#pragma unroll
        for (int j = 0; j < 8; j++) acc[e][j] = 0ull;

    float4 ra[2];

#pragma unroll
    for (int i = 0; i < 2; i++)
        ra[i] = *(const float4*)(A + (size_t)(bm + amr[i]) * NI_ + akc);
#pragma unroll
    for (int i = 0; i < 2; i++) {
        unsigned dst = (unsigned)__cvta_generic_to_shared(Bs + bkr[i] * 128 + bnc);
        asm volatile("cp.async.cg.shared.global [%0], [%1], 16;"
                     :: "r"(dst), "l"(W + (size_t)bkr[i] * N_ + bn0 + bnc));
    }
    asm volatile("cp.async.commit_group;");
#pragma unroll
    for (int i = 0; i < 2; i++) {
        As[(akc + 0) * ASTRIDE + amr[i]] = ra[i].x;
        As[(akc + 1) * ASTRIDE + amr[i]] = ra[i].y;
        As[(akc + 2) * ASTRIDE + amr[i]] = ra[i].z;
        As[(akc + 3) * ASTRIDE + amr[i]] = ra[i].w;
    }
    asm volatile("cp.async.wait_group 0;");
    __syncthreads();

    for (int kt = 0; kt < 16; kt++) {
        const int st = kt & 1;
        if (kt < 15) {
#pragma unroll
            for (int i = 0; i < 2; i++)
                ra[i] = *(const float4*)(A + (size_t)(bm + amr[i]) * NI_
                                           + (kt + 1) * 16 + akc);
#pragma unroll
            for (int i = 0; i < 2; i++) {
                unsigned dst = (unsigned)__cvta_generic_to_shared(
                    Bs + (st ^ 1) * (16 * 128) + bkr[i] * 128 + bnc);
                asm volatile("cp.async.cg.shared.global [%0], [%1], 16;"
                    :: "r"(dst),
                       "l"(W + (size_t)((kt+1)*16 + bkr[i]) * N_ + bn0 + bnc));
            }
            asm volatile("cp.async.commit_group;");
        }

        const float* as = As + st * (16 * ASTRIDE);
        const float* bs = Bs + st * (16 * 128);
#pragma unroll
        for (int k = 0; k < 16; k++) {
            ulonglong2 aA = *(const ulonglong2*)(as + k * ASTRIDE + m0);
            ulonglong2 aB = *(const ulonglong2*)(as + k * ASTRIDE + m0 + 4);
            unsigned long long am4[4] = { aA.x, aA.y, aB.x, aB.y };
            float4 bv0 = *(const float4*)(bs + k * 128 + (tn << 2));
            float4 bv1 = *(const float4*)(bs + k * 128 + 64 + (tn << 2));
            unsigned long long b[8];
            PACK2(b[0], bv0.x); PACK2(b[1], bv0.y);
            PACK2(b[2], bv0.z); PACK2(b[3], bv0.w);
            PACK2(b[4], bv1.x); PACK2(b[5], bv1.y);
            PACK2(b[6], bv1.z); PACK2(b[7], bv1.w);
#pragma unroll
            for (int e = 0; e < 4; e++)
#pragma unroll
                for (int j = 0; j < 8; j++)
                    FFMA2(acc[e][j], am4[e], b[j], acc[e][j]);
        }
        if (kt == 15) break;

#pragma unroll
        for (int i = 0; i < 2; i++) {
            float* ad = As + (st ^ 1) * (16 * ASTRIDE);
            ad[(akc + 0) * ASTRIDE + amr[i]] = ra[i].x;
            ad[(akc + 1) * ASTRIDE + amr[i]] = ra[i].y;
            ad[(akc + 2) * ASTRIDE + amr[i]] = ra[i].z;
            ad[(akc + 3) * ASTRIDE + amr[i]] = ra[i].w;
        }
        asm volatile("cp.async.wait_group 0;");
        __syncthreads();
    }

    unsigned long long* op = g_xw;
    const int pbase = (bm + m0) >> 1;
#pragma unroll
    for (int e = 0; e < 4; e++) {
        size_t prow = (size_t)(pbase + e) * 256 + bn0;
        ulonglong2 s0, s1, s2, s3;
        s0.x = acc[e][0]; s0.y = acc[e][1];
        s1.x = acc[e][2]; s1.y = acc[e][3];
        s2.x = acc[e][4]; s2.y = acc[e][5];
        s3.x = acc[e][6]; s3.y = acc[e][7];
        *(ulonglong2*)(op + prow + (tn << 2))          = s0;
        *(ulonglong2*)(op + prow + (tn << 2) + 2)      = s1;
        *(ulonglong2*)(op + prow + 64 + (tn << 2))     = s2;
        *(ulonglong2*)(op + prow + 64 + (tn << 2) + 2) = s3;
    }
}

// ===========================================================================
// Kernel 2: paired-thread LSNN scan. 128 CTAs x 512 threads.
// Lanes 2i/2i+1 (same warp) co-own neuron n = tid>>1: each half does 16 of
// the 32 block-gather loads + half the dense high rows; pair combines with
// one exact shfl.xor(1). Both lanes hold bit-identical state. 4 warps/SMSP.
// Flat list + two-phase build (R4 style), 14 counting warps, 2 bars/step.
// ===========================================================================
#define WROWS 222
#define SENT  (222 << 10)
#define LCAP  232
// float offsets
#define OFF_FLAT (223*256)            // 2*232 ints
#define OFF_CNT  (OFF_FLAT + 2*LCAP)  // 16 ints (14 used; 14,15 = 0)
#define OFF_TOT  (OFF_CNT + 16)       // 2 + 2 pad
#define OFF_ZHI  (OFF_TOT + 4)        // 2*36 floats (34 used; 34,35 stay 0)
#define SCAN_SMEM ((OFF_ZHI + 72) * 4)   // 230,576 B

__global__ void __launch_bounds__(512, 1)
lsnn_scan(const float* __restrict__ w_rec,
          const float* __restrict__ z0,  const float* __restrict__ v0,
          const float* __restrict__ a0,  const float* __restrict__ lsd0,
          float* __restrict__ out, float decay_v, float decay_a)
{
    extern __shared__ float sm[];
    float* w_sm  = sm;                       // [223][256], row 222 = zeros
    int*   flatL = (int*)(sm + OFF_FLAT);    // [2][232]
    int*   cntS  = (int*)(sm + OFF_CNT);     // [16]
    int*   totS  = (int*)(sm + OFF_TOT);     // [2]
    float* zhi   = sm + OFF_ZHI;             // [2][36]

    const int tid  = threadIdx.x;
    const int n    = tid >> 1;               // neuron
    const int h    = tid & 1;                // half
    const int w    = tid >> 5;               // warp (0..15): neurons 16w..16w+15
    const int lane = tid & 31;
    const int b    = blockIdx.x;

    // weights rows 0..221 -> smem (512 threads)
    {
        const float4* src = (const float4*)w_rec;
        float4*       dst = (float4*)w_sm;
        for (int i = tid; i < WROWS * 64; i += 512) dst[i] = src[i];
    }
    // dense high rows 222..255: 17 f32x2 pairs split even(0..8)/odd(9..16).
    // Each thread loads 9 pairs; odd half's 9th (j2==17) is a zero dummy.
    unsigned long long wp[9];
#pragma unroll
    for (int j = 0; j < 9; j++) {
        int j2 = h * 9 + j;
        float wlo = 0.f, whi = 0.f;
        if (j2 < 17) {
            wlo = w_rec[(size_t)(222 + 2*j2) * 256 + n];
            whi = w_rec[(size_t)(223 + 2*j2) * 256 + n];
            if (n == 222 + 2*j2) wlo = 0.f;
            if (n == 223 + 2*j2) whi = 0.f;
        }
        PACKAB(wp[j], wlo, whi);
    }
    if (tid < 256) w_sm[222 * 256 + tid] = 0.f;   // zero sentinel row
    if (tid < 16)  cntS[tid] = 0;                 // incl. unused 14,15
    if (tid < 2)   totS[tid] = 0;
    if (tid < 72)  zhi[tid] = 0.f;                // incl. pad slots 34,35
    __syncthreads();
    if (tid < WROWS) w_sm[tid * 256 + tid] = 0.f; // diag mask

    // state (both lanes of a pair hold identical copies)
    float z_self = z0[b * N_ + n];
    float v      = v0[b * N_ + n];
    float a      = a0[b * N_ + n];
    float lsd    = lsd0[b * N_ + n];

    // ---- initial build (buffer 0): two-phase flat list ----
    unsigned mseg0;
    {
        unsigned m     = __ballot_sync(0xffffffffu, z_self != 0.f);
        unsigned meven = m & 0x55555555u;
        mseg0 = (w == 13) ? (meven & 0x05555555u) : meven;   // drop rows 222,223
        if (w < 14) { if (lane == 0) cntS[w] = __popc(mseg0); }
        if (h == 0 && n >= 222) zhi[n - 222] = z_self;
    }
    __syncthreads();
    {
        int4 cA = *(const int4*)&cntS[0];
        int4 cB = *(const int4*)&cntS[4];
        int4 cC = *(const int4*)&cntS[8];
        int4 cD = *(const int4*)&cntS[12];
        if (w < 14) {
            int start = 0;
            if (w > 0)  start += cA.x; if (w > 1)  start += cA.y;
            if (w > 2)  start += cA.z; if (w > 3)  start += cA.w;
            if (w > 4)  start += cB.x; if (w > 5)  start += cB.y;
            if (w > 6)  start += cB.z; if (w > 7)  start += cB.w;
            if (w > 8)  start += cC.x; if (w > 9)  start += cC.y;
            if (w > 10) start += cC.z; if (w > 11) start += cC.w;
            if (w > 12) start += cD.x;
            if ((mseg0 >> lane) & 1u) {
                int r = __popc(mseg0 & ((1u << lane) - 1u));
                flatL[start + r] = n << 10;
            }
        } else if (w == 14) {
            int tt = cA.x + cA.y + cA.z + cA.w + cB.x + cB.y + cB.z + cB.w
                   + cC.x + cC.y + cC.z + cC.w + cD.x + cD.y;
            if (lane < 8 || tt + lane < 32) flatL[tt + lane] = SENT;
            if (lane == 0) totS[0] = tt;
        }
    }

    const float omdv = 1.f - decay_v;
    const float omda = 1.f - decay_a;
    const char*  wpn = (const char*)w_sm + (n << 2);
    const float* xwb = (const float*)g_xw;
    const int    mb0 = b * T_;
    const int    twon = n << 1;

#define XW_LD(tt_) __ldcs(xwb + (((size_t)((mb0 + (tt_)) >> 1)) << 9) + twon + ((mb0 + (tt_)) & 1))
    float xw_c  = XW_LD(0);
    float xw_n1 = XW_LD(1);
    __syncthreads();

#pragma unroll 1
    for (int t = 0; t < T_; t++) {
        const int rb = t & 1, wb = rb ^ 1;

        float xw_n2 = (t + 2 < T_) ? XW_LD(t + 2) : 0.f;

        const int  tot = totS[rb];
        const int* fl  = flatL + rb * LCAP;
        const unsigned long long* zp =
            (const unsigned long long*)(zhi + rb * 36);

        // each half reads its 4 chunks (entries h*16 .. h*16+15)
        const int4* fc = (const int4*)fl + (h << 2);
        int4 c0 = fc[0], c1 = fc[1], c2 = fc[2], c3 = fc[3];

        // precompute next-state terms independent of i_in
        float new_a  = __fadd_rn(__fmul_rn(decay_a, a), __fmul_rn(omda, z_self));
        float thr    = __fadd_rn(0.03f, __fmul_rn(new_a, 1.8f));
        float base   = __fadd_rn(__fmul_rn(decay_v, v), __fmul_rn(-thr, z_self));
        int   nonref = (lsd >= 2.f);
        float lsp1   = __fadd_rn(lsd, 1.f);

        // half of the dense high-row dot (9 pairs; dummy pair adds exact 0)
        unsigned long long h0, h1;
        PACKAB(h0, 0.f, 0.f); PACKAB(h1, 0.f, 0.f);
#pragma unroll
        for (int j = 0; j < 8; j += 2) {
            FFMA2(h0, zp[h * 9 + j],     wp[j],     h0);
            FFMA2(h1, zp[h * 9 + j + 1], wp[j + 1], h1);
        }
        FFMA2(h0, zp[h * 9 + 8], wp[8], h0);

        // 16 gather loads (this half's entries; sentinels add exact 0)
        float av[4] = {0.f, 0.f, 0.f, 0.f};
        av[0] += *(const float*)(wpn + c0.x);
        av[1] += *(const float*)(wpn + c0.y);
        av[2] += *(const float*)(wpn + c0.z);
        av[3] += *(const float*)(wpn + c0.w);
        av[0] += *(const float*)(wpn + c1.x);
        av[1] += *(const float*)(wpn + c1.y);
        av[2] += *(const float*)(wpn + c1.z);
        av[3] += *(const float*)(wpn + c1.w);
        av[0] += *(const float*)(wpn + c2.x);
        av[1] += *(const float*)(wpn + c2.y);
        av[2] += *(const float*)(wpn + c2.z);
        av[3] += *(const float*)(wpn + c2.w);
        av[0] += *(const float*)(wpn + c3.x);
        av[1] += *(const float*)(wpn + c3.y);
        av[2] += *(const float*)(wpn + c3.z);
        av[3] += *(const float*)(wpn + c3.w);

        // rare tail (tot > 32): odd half only
        if (h) {
#pragma unroll 1
            for (int j = 32; j < tot; j += 4) {
                int4 o = *(const int4*)(fl + j);
                av[0] += *(const float*)(wpn + o.x);
                av[1] += *(const float*)(wpn + o.y);
                av[2] += *(const float*)(wpn + o.z);
                av[3] += *(const float*)(wpn + o.w);
            }
        }

        // half sum (gather + dense half)
        float2 f0 = *(float2*)&h0, f1 = *(float2*)&h1;
        float sh = __fadd_rn(
            __fadd_rn(__fadd_rn(av[0], av[1]), __fadd_rn(av[2], av[3])),
            __fadd_rn(__fadd_rn(f0.x, f0.y), __fadd_rn(f1.x, f1.y)));

        // pair combine (exact; fixed even+odd order on both lanes)
        float sp = __shfl_xor_sync(0xffffffffu, sh, 1);
        float evenS = h ? sp : sh;
        float oddS  = h ? sh : sp;
        const float i_in = __fadd_rn(__fadd_rn(xw_c, evenS), oddS);

        float new_v = __fmaf_rn(omdv, i_in, base);
        int   spk   = (new_v > thr) && nonref;
        float zf    = spk ? 1.f : 0.f;

        // phase 1: counts + high-row staging
        unsigned m     = __ballot_sync(0xffffffffu, spk);
        unsigned meven = m & 0x55555555u;
        unsigned mseg  = (w == 13) ? (meven & 0x05555555u) : meven;
        if (w < 14) { if (lane == 0) cntS[w] = __popc(mseg); }
        if (h == 0 && n >= 222) zhi[wb * 36 + (n - 222)] = zf;

        float new_lsd = __fmul_rn(lsp1, __fadd_rn(1.f, -zf));
        float v_sc    = __fdividef(__fadd_rn(new_v, -thr), thr);
        __syncthreads();

        // outputs: even lane -> z, v; odd lane -> thr, v_sc
        const size_t ob = ((size_t)t * B_ + b) * N_ + n;
        if (h == 0) {
            __stcs(out + ob,        zf);
            __stcs(out + TBN_ + ob, new_v);
        } else {
            __stcs(out + 2 * TBN_ + ob, thr);
            __stcs(out + 3 * TBN_ + ob, v_sc);
        }

        // phase 2: prefix + flat write + sentinels (into buffer wb)
        {
            int4 cA = *(const int4*)&cntS[0];
            int4 cB = *(const int4*)&cntS[4];
            int4 cC = *(const int4*)&cntS[8];
            int4 cD = *(const int4*)&cntS[12];
            if (w < 14) {
                int start = 0;
                if (w > 0)  start += cA.x; if (w > 1)  start += cA.y;
                if (w > 2)  start += cA.z; if (w > 3)  start += cA.w;
                if (w > 4)  start += cB.x; if (w > 5)  start += cB.y;
                if (w > 6)  start += cB.z; if (w > 7)  start += cB.w;
                if (w > 8)  start += cC.x; if (w > 9)  start += cC.y;
                if (w > 10) start += cC.z; if (w > 11) start += cC.w;
                if (w > 12) start += cD.x;
                if ((mseg >> lane) & 1u) {
                    int r = __popc(mseg & ((1u << lane) - 1u));
                    flatL[wb * LCAP + start + r] = n << 10;
                }
            } else if (w == 14) {
                int tt = cA.x + cA.y + cA.z + cA.w + cB.x + cB.y + cB.z + cB.w
                       + cC.x + cC.y + cC.z + cC.w + cD.x + cD.y;
                if (lane < 8 || tt + lane < 32)
                    flatL[wb * LCAP + tt + lane] = SENT;
                if (lane == 0) totS[wb] = tt;
            }
        }

        z_self = zf; v = new_v; a = new_a; lsd = new_lsd;
        xw_c = xw_n1; xw_n1 = xw_n2;
        __syncthreads();
    }
#undef XW_LD
}

// ---------------------------------------------------------------------------
// Launcher (graph-capturable)
// ---------------------------------------------------------------------------
extern "C" void kernel_launch(void* const* d_in, const int* in_sizes, int n_in,
                              void* d_out, int out_size)
{
    const float* x     = (const float*)d_in[0];
    const float* w_in  = (const float*)d_in[1];
    const float* w_rec = (const float*)d_in[2];
    const float* z0    = (const float*)d_in[3];
    const float* v0    = (const float*)d_in[4];
    const float* a0    = (const float*)d_in[5];
    const float* lsd0  = (const float*)d_in[6];
    float* out = (float*)d_out;

    const float decay_v = expf(-1.0f / 20.0f);
    const float decay_a = expf(-1.0f / 20.0f);

    cudaFuncSetAttribute(gemm_xw,
                         cudaFuncAttributeMaxDynamicSharedMemorySize, GEMM_SMEM);
    cudaFuncSetAttribute(lsnn_scan,
                         cudaFuncAttributeMaxDynamicSharedMemorySize, SCAN_SMEM);

    dim3 g1(M_ / 128, 2);
    gemm_xw<<<g1, 256, GEMM_SMEM>>>(x, w_in);
    lsnn_scan<<<B_, 512, SCAN_SMEM>>>(w_rec, z0, v0, a0, lsd0, out,
                                      decay_v, decay_a);
}